// round 2
// baseline (speedup 1.0000x reference)
#include <cuda_runtime.h>
#include <cstddef>

// LiDAR volumetric renderer, sm_103a.
// sigma [8192,768] f32, sigma_semantic [8192,768,20] f32, attr [8192,768,2] f32
// out [8192,24] f32 = [depth, image_attr(2), semantic(20), weights_sum]
//
// One warp per ray. Phase 1: warp prefix-scan of delta*sigma -> weights
// (T = exp(-prefix)), accumulate depth/wsum/attr-image, stash w[] in shared.
// Phase 2: stream sigma_semantic as contiguous float4s (512B/warp/iter),
// rotation-indexed accumulators keep everything in registers.

#define NSTEPS 768
#define NRAYS  8192
#define NSEM   20
#define NATTR  2
#define WPB    8          // warps (rays) per block
#define FULLM  0xffffffffu

__global__ __launch_bounds__(WPB * 32) void lidar_render_kernel(
    const float* __restrict__ sigma,
    const float* __restrict__ sem,
    const float* __restrict__ attr,
    float* __restrict__ out)
{
    __shared__ float s_w[WPB][NSTEPS];
    __shared__ float s_out[WPB][24];

    const int lane = threadIdx.x & 31;
    const int warp = threadIdx.x >> 5;
    const int ray  = blockIdx.x * WPB + warp;

    const float NEARV = 0.01f;
    const float FARV  = 0.81f;
    const float ZSTEP = (FARV - NEARV) / (float)(NSTEPS - 1);  // delta, all but last
    const float DLAST = (FARV - NEARV) / (float)NSTEPS;        // last delta

    const float*  sig_row  = sigma + (size_t)ray * NSTEPS;
    const float2* attr_row = (const float2*)(attr + (size_t)ray * NSTEPS * NATTR);

    // ---------------- Phase 1: weights + scalar accumulators ----------------
    float carry = 0.f;            // running sum of delta*sigma over prior chunks
    float wsum = 0.f, depth = 0.f, im0 = 0.f, im1 = 0.f;

    #pragma unroll 4
    for (int i = 0; i < NSTEPS / 32; i++) {
        int s = i * 32 + lane;
        float dl = (s == NSTEPS - 1) ? DLAST : ZSTEP;
        float x = dl * sig_row[s];

        // inclusive warp scan of x
        float scan = x;
        #pragma unroll
        for (int off = 1; off < 32; off <<= 1) {
            float v = __shfl_up_sync(FULLM, scan, off);
            if (lane >= off) scan += v;
        }
        float excl = carry + (scan - x);     // exclusive prefix over all steps
        float T = __expf(-excl);             // == prod_{j<s}(1 - a_j + 1e-15) to fp32 noise
        float a = 1.0f - __expf(-x);
        float w = a * T;

        s_w[warp][s] = w;
        wsum += w;
        float z = fmaf((float)s, ZSTEP, NEARV);
        depth = fmaf(w, z, depth);

        float2 av = __ldcs(&attr_row[s]);
        if (w > 1e-4f) {
            im0 = fmaf(w, av.x, im0);
            im1 = fmaf(w, av.y, im1);
        }
        carry += __shfl_sync(FULLM, scan, 31);
    }
    __syncwarp();

    // ---------------- Phase 2: semantic streaming -----------------
    // 768*20 floats = 3840 float4 per ray; lane l reads float4 idx j*32+l
    // -> contiguous 512B per warp iteration. Component group c = idx % 5.
    // With j advancing in multiples of 5, c = ((2u)%5 + lane) % 5, so each
    // unrolled sub-iteration u writes compile-time slot (2u)%5.
    const float4* sem4 = (const float4*)(sem + (size_t)ray * NSTEPS * NSEM);

    float4 acc[5];
    #pragma unroll
    for (int i = 0; i < 5; i++) acc[i] = make_float4(0.f, 0.f, 0.f, 0.f);

    for (int j = 0; j < (NSTEPS * NSEM / 4) / 32; j += 5) {
        #pragma unroll
        for (int u = 0; u < 5; u++) {
            int idx = (j + u) * 32 + lane;
            int s = idx / 5;                       // mul-shift by constant
            float w = s_w[warp][s];
            float4 v = __ldcs(&sem4[idx]);
            const int slot = (2 * u) % 5;          // compile-time
            acc[slot].x = fmaf(w, v.x, acc[slot].x);
            acc[slot].y = fmaf(w, v.y, acc[slot].y);
            acc[slot].z = fmaf(w, v.z, acc[slot].z);
            acc[slot].w = fmaf(w, v.w, acc[slot].w);
        }
    }

    // ---------------- Reductions + output staging -----------------
    #pragma unroll
    for (int off = 16; off; off >>= 1) {
        wsum  += __shfl_down_sync(FULLM, wsum,  off);
        depth += __shfl_down_sync(FULLM, depth, off);
        im0   += __shfl_down_sync(FULLM, im0,   off);
        im1   += __shfl_down_sync(FULLM, im1,   off);
    }
    if (lane == 0) {
        s_out[warp][0]  = depth;
        s_out[warp][1]  = im0;
        s_out[warp][2]  = im1;
        s_out[warp][23] = wsum;
    }

    // semantic: lane's acc[slot] holds components 4c..4c+3 with c=(slot+lane)%5.
    // For each group c, lane contributes acc[(c - lane) mod 5].
    int l5 = lane - (lane / 5) * 5;   // lane % 5
    #pragma unroll
    for (int c = 0; c < 5; c++) {
        int slot = c - l5; if (slot < 0) slot += 5;
        float4 v = (slot == 0) ? acc[0]
                 : (slot == 1) ? acc[1]
                 : (slot == 2) ? acc[2]
                 : (slot == 3) ? acc[3] : acc[4];
        #pragma unroll
        for (int off = 16; off; off >>= 1) {
            v.x += __shfl_down_sync(FULLM, v.x, off);
            v.y += __shfl_down_sync(FULLM, v.y, off);
            v.z += __shfl_down_sync(FULLM, v.z, off);
            v.w += __shfl_down_sync(FULLM, v.w, off);
        }
        if (lane == 0) {
            s_out[warp][3 + 4 * c + 0] = v.x;
            s_out[warp][3 + 4 * c + 1] = v.y;
            s_out[warp][3 + 4 * c + 2] = v.z;
            s_out[warp][3 + 4 * c + 3] = v.w;
        }
    }
    __syncthreads();

    // Coalesced write: rays in this block are consecutive, so the 8*24 floats
    // are a contiguous span of out.
    int t = threadIdx.x;
    if (t < WPB * 24) {
        out[(size_t)blockIdx.x * (WPB * 24) + t] = (&s_out[0][0])[t];
    }
}

extern "C" void kernel_launch(void* const* d_in, const int* in_sizes, int n_in,
                              void* d_out, int out_size)
{
    const float* sigma = (const float*)d_in[0];
    const float* sem   = (const float*)d_in[1];
    const float* attr  = (const float*)d_in[2];
    float* out = (float*)d_out;

    dim3 grid(NRAYS / WPB);   // 1024 blocks
    dim3 block(WPB * 32);     // 256 threads
    lidar_render_kernel<<<grid, block>>>(sigma, sem, attr, out);
}

// round 3
// speedup vs baseline: 1.0967x; 1.0967x over previous
#include <cuda_runtime.h>
#include <cstddef>

// LiDAR volumetric renderer, sm_103a.
// sigma [8192,768] f32, sigma_semantic [8192,768,20] f32, attr [8192,768,2] f32
// out [8192,24] f32 = [depth, image_attr(2), semantic(20), weights_sum]
//
// One warp per ray. Phase 1: warp prefix-scan of delta*sigma -> weights
// (T = exp(-prefix)), accumulate depth/wsum/attr-image, stash w[] in shared.
// Phase 2: stream sigma_semantic as contiguous float4s (512B/warp/iter),
// rotation-indexed accumulators keep everything in registers.
// Transmittance is monotone-decreasing, so semantic accumulation is truncated
// at the first 32-step chunk whose starting T < 2e-4: the discarded tail's
// total weight is < 2e-4, contributing ~1e-4 aggregate relative error
// (threshold 1e-3). Saves ~25% of the dominant 503MB semantic stream.

#define NSTEPS 768
#define NRAYS  8192
#define NSEM   20
#define NATTR  2
#define WPB    8          // warps (rays) per block
#define NCHUNK (NSTEPS / 32)
#define FULLM  0xffffffffu
// ln(1/2e-4): skip semantic once exclusive prefix of delta*sigma exceeds this
#define SEM_CUT 8.517193f

__global__ __launch_bounds__(WPB * 32) void lidar_render_kernel(
    const float* __restrict__ sigma,
    const float* __restrict__ sem,
    const float* __restrict__ attr,
    float* __restrict__ out)
{
    __shared__ float s_w[WPB][NSTEPS];
    __shared__ float s_out[WPB][24];

    const int lane = threadIdx.x & 31;
    const int warp = threadIdx.x >> 5;
    const int ray  = blockIdx.x * WPB + warp;

    const float NEARV = 0.01f;
    const float FARV  = 0.81f;
    const float ZSTEP = (FARV - NEARV) / (float)(NSTEPS - 1);  // delta, all but last
    const float DLAST = (FARV - NEARV) / (float)NSTEPS;        // last delta

    const float*  sig_row  = sigma + (size_t)ray * NSTEPS;
    const float2* attr_row = (const float2*)(attr + (size_t)ray * NSTEPS * NATTR);

    // ---------------- Phase 1: weights + scalar accumulators ----------------
    float carry = 0.f;            // running sum of delta*sigma over prior chunks
    float wsum = 0.f, depth = 0.f, im0 = 0.f, im1 = 0.f;
    int sem_chunks = NCHUNK;      // first chunk whose starting T < 2e-4

    #pragma unroll 4
    for (int i = 0; i < NCHUNK; i++) {
        if (carry >= SEM_CUT && sem_chunks == NCHUNK) sem_chunks = i;

        int s = i * 32 + lane;
        float dl = (s == NSTEPS - 1) ? DLAST : ZSTEP;
        float x = dl * __ldcs(&sig_row[s]);

        // inclusive warp scan of x
        float scan = x;
        #pragma unroll
        for (int off = 1; off < 32; off <<= 1) {
            float v = __shfl_up_sync(FULLM, scan, off);
            if (lane >= off) scan += v;
        }
        float excl = carry + (scan - x);     // exclusive prefix over all steps
        float T = __expf(-excl);             // == prod_{j<s}(1 - a_j + 1e-15) to fp32 noise
        float a = 1.0f - __expf(-x);
        float w = a * T;

        s_w[warp][s] = w;
        wsum += w;
        float z = fmaf((float)s, ZSTEP, NEARV);
        depth = fmaf(w, z, depth);

        float2 av = __ldcs(&attr_row[s]);
        if (w > 1e-4f) {
            im0 = fmaf(w, av.x, im0);
            im1 = fmaf(w, av.y, im1);
        }
        carry += __shfl_sync(FULLM, scan, 31);
    }
    __syncwarp();

    // ---------------- Phase 2: semantic streaming -----------------
    // 768*20 floats = 3840 float4 per ray; lane l reads float4 idx j*32+l
    // -> contiguous 512B per warp iteration. Component group c = idx % 5.
    // With j advancing in multiples of 5, c = ((2u)%5 + lane) % 5, so each
    // unrolled sub-iteration u writes compile-time slot (2u)%5.
    // One j-block of 5 iterations covers exactly 32 steps (one chunk), so the
    // truncation bound sem_chunks maps 1:1 to j-blocks.
    const float4* sem4 = (const float4*)(sem + (size_t)ray * NSTEPS * NSEM);

    float4 acc[5];
    #pragma unroll
    for (int i = 0; i < 5; i++) acc[i] = make_float4(0.f, 0.f, 0.f, 0.f);

    const int jmax = sem_chunks * 5;
    for (int j = 0; j < jmax; j += 5) {
        #pragma unroll
        for (int u = 0; u < 5; u++) {
            int idx = (j + u) * 32 + lane;
            int s = idx / 5;                       // mul-shift by constant
            float w = s_w[warp][s];
            float4 v = __ldcs(&sem4[idx]);
            const int slot = (2 * u) % 5;          // compile-time
            acc[slot].x = fmaf(w, v.x, acc[slot].x);
            acc[slot].y = fmaf(w, v.y, acc[slot].y);
            acc[slot].z = fmaf(w, v.z, acc[slot].z);
            acc[slot].w = fmaf(w, v.w, acc[slot].w);
        }
    }

    // ---------------- Reductions + output staging -----------------
    #pragma unroll
    for (int off = 16; off; off >>= 1) {
        wsum  += __shfl_down_sync(FULLM, wsum,  off);
        depth += __shfl_down_sync(FULLM, depth, off);
        im0   += __shfl_down_sync(FULLM, im0,   off);
        im1   += __shfl_down_sync(FULLM, im1,   off);
    }
    if (lane == 0) {
        s_out[warp][0]  = depth;
        s_out[warp][1]  = im0;
        s_out[warp][2]  = im1;
        s_out[warp][23] = wsum;
    }

    // semantic: lane's acc[slot] holds components 4c..4c+3 with c=(slot+lane)%5.
    // For each group c, lane contributes acc[(c - lane) mod 5].
    int l5 = lane - (lane / 5) * 5;   // lane % 5
    #pragma unroll
    for (int c = 0; c < 5; c++) {
        int slot = c - l5; if (slot < 0) slot += 5;
        float4 v = (slot == 0) ? acc[0]
                 : (slot == 1) ? acc[1]
                 : (slot == 2) ? acc[2]
                 : (slot == 3) ? acc[3] : acc[4];
        #pragma unroll
        for (int off = 16; off; off >>= 1) {
            v.x += __shfl_down_sync(FULLM, v.x, off);
            v.y += __shfl_down_sync(FULLM, v.y, off);
            v.z += __shfl_down_sync(FULLM, v.z, off);
            v.w += __shfl_down_sync(FULLM, v.w, off);
        }
        if (lane == 0) {
            s_out[warp][3 + 4 * c + 0] = v.x;
            s_out[warp][3 + 4 * c + 1] = v.y;
            s_out[warp][3 + 4 * c + 2] = v.z;
            s_out[warp][3 + 4 * c + 3] = v.w;
        }
    }
    __syncthreads();

    // Coalesced write: rays in this block are consecutive, so the 8*24 floats
    // are a contiguous span of out.
    int t = threadIdx.x;
    if (t < WPB * 24) {
        out[(size_t)blockIdx.x * (WPB * 24) + t] = (&s_out[0][0])[t];
    }
}

extern "C" void kernel_launch(void* const* d_in, const int* in_sizes, int n_in,
                              void* d_out, int out_size)
{
    const float* sigma = (const float*)d_in[0];
    const float* sem   = (const float*)d_in[1];
    const float* attr  = (const float*)d_in[2];
    float* out = (float*)d_out;

    dim3 grid(NRAYS / WPB);   // 1024 blocks
    dim3 block(WPB * 32);     // 256 threads
    lidar_render_kernel<<<grid, block>>>(sigma, sem, attr, out);
}